// round 11
// baseline (speedup 1.0000x reference)
#include <cuda_runtime.h>
#include <cuda_bf16.h>
#include <cstdint>

#define NPTS 4096
#define DIMS 1024
#define NCLS 64
#define EPSV 0.1f

#define RCH  64                 // row chunks for phase-1 partials
#define RPC  (NPTS / RCH)       // 64 rows per chunk
#define DCH  64                 // dims per phase-1 block
#define NDCH (DIMS / DCH)       // 16

// k_main tiling (int8 mma.sync m16n8k32)
#define BM   256
#define BN   128
#define BK   128                // int8 elems per chunk = 128 B per row
#define NCH  (DIMS / BK)        // 8 chunks
#define NTILES 272              // triangle tiles: sum_{bi<16} (32 - 2*bi)
#define LSTRB 144               // smem row stride in bytes (128 + 16 pad)
#define A_BYTES (BM * LSTRB)    // 36864
#define B_BYTES (BN * LSTRB)    // 18432
#define STGB  (A_BYTES + B_BYTES)  // 55296 B per stage
#define NSTG  3
#define DSMEM_BYTES (NSTG * STGB)  // 165888 B

// ---- static device scratch (no allocations allowed) ----
__device__ int      g_counts[NCLS];
__device__ float    g_spart[RCH][DIMS][NCLS];   // 16 MB partial class sums
__device__ float    g_Apart[RCH][DIMS];
__device__ float    g_Qpart[RCH][DIMS];
__device__ float    g_s[NCLS][DIMS];
__device__ float    g_w[DIMS];
__device__ signed char g_xq[(size_t)NPTS * DIMS];   // int8(x / sA_i)
__device__ signed char g_xwq[(size_t)NPTS * DIMS];  // int8(w*x / sB_i)
__device__ float    g_sA[NPTS];                 // per-row scale of x
__device__ float    g_sB[NPTS];                 // per-row scale of w*x
__device__ float    g_sq[NPTS];                 // sq_i = sum_d w_d x_id^2 (fp32 exact)
__device__ float    g_P[NCLS];
__device__ float    g_wss[NCLS];
__device__ double   g_pairsum;

// ---------------- helpers ----------------
__device__ __forceinline__ uint32_t smem_u32(const void* p) {
    uint32_t a;
    asm("{ .reg .u64 t; cvta.to.shared.u64 t, %1; cvt.u32.u64 %0, t; }" : "=r"(a) : "l"(p));
    return a;
}
__device__ __forceinline__ void cp16(uint32_t dst, const void* src) {
    asm volatile("cp.async.cg.shared.global [%0], [%1], 16;" :: "r"(dst), "l"(src) : "memory");
}
__device__ __forceinline__ void ldm_x4(uint32_t& r0, uint32_t& r1, uint32_t& r2, uint32_t& r3,
                                       uint32_t addr) {
    asm volatile("ldmatrix.sync.aligned.m8n8.x4.shared.b16 {%0,%1,%2,%3}, [%4];"
                 : "=r"(r0), "=r"(r1), "=r"(r2), "=r"(r3) : "r"(addr));
}
__device__ __forceinline__ void mma_s8(int* c, uint32_t a0, uint32_t a1, uint32_t a2,
                                       uint32_t a3, uint32_t b0, uint32_t b1) {
    asm volatile("mma.sync.aligned.m16n8k32.row.col.s32.s8.s8.s32 "
                 "{%0,%1,%2,%3}, {%4,%5,%6,%7}, {%8,%9}, {%0,%1,%2,%3};"
                 : "+r"(c[0]), "+r"(c[1]), "+r"(c[2]), "+r"(c[3])
                 : "r"(a0), "r"(a1), "r"(a2), "r"(a3), "r"(b0), "r"(b1));
}

// ------------------------------------------------------------------
__global__ void k_zero() {
    int t = threadIdx.x;
    if (t < NCLS) { g_counts[t] = 0; g_P[t] = 0.f; }
    if (t == NCLS) g_pairsum = 0.0;
}

__global__ void k_count(const int* __restrict__ tgt) {
    int i = blockIdx.x * blockDim.x + threadIdx.x;
    if (i < NPTS) atomicAdd(&g_counts[tgt[i]], 1);
}

__global__ void k_phase1(const float* __restrict__ X, const int* __restrict__ tgt) {
    __shared__ float s_sh[NCLS * DCH];
    __shared__ float cnt_sh[NCLS];
    __shared__ int   tg_sh[RPC];
    int t  = threadIdx.x;                // 0..63
    int dc = blockIdx.x, rc = blockIdx.y;

    for (int i = t; i < NCLS * DCH; i += 64) s_sh[i] = 0.f;
    cnt_sh[t] = (float)g_counts[t];
    if (t < RPC) tg_sh[t] = tgt[rc * RPC + t];
    __syncthreads();

    const float* xp = X + (size_t)(rc * RPC) * DIMS + dc * DCH + t;
    float aacc = 0.f, qacc = 0.f;
    #pragma unroll 8
    for (int r = 0; r < RPC; r++) {
        float v = xp[(size_t)r * DIMS];
        int   k = tg_sh[r];
        s_sh[k * DCH + t] += v;
        float v2 = v * v;
        qacc += v2;
        aacc = fmaf(cnt_sh[k], v2, aacc);
    }
    __syncthreads();

    int d = dc * DCH + t;
    #pragma unroll
    for (int k4 = 0; k4 < NCLS; k4 += 4) {
        float4 v = make_float4(s_sh[(k4 + 0) * DCH + t], s_sh[(k4 + 1) * DCH + t],
                               s_sh[(k4 + 2) * DCH + t], s_sh[(k4 + 3) * DCH + t]);
        *(float4*)&g_spart[rc][d][k4] = v;
    }
    g_Apart[rc][d] = aacc;
    g_Qpart[rc][d] = qacc;
}

// 256 threads: 4 rc-groups x 64 classes, 4x the memory-level parallelism.
__global__ void k_reduce_w() {
    int d = blockIdx.x, t = threadIdx.x;
    int k = t & 63, rg = t >> 6;         // class, rc-group

    float s = 0.f;
    #pragma unroll
    for (int rc = rg * 16; rc < rg * 16 + 16; rc++) s += g_spart[rc][d][k];
    __shared__ float sp[4][NCLS];
    sp[rg][k] = s;
    __syncthreads();

    __shared__ float sh1[NCLS], sh2[NCLS], sh3[NCLS], sh4[NCLS], sh5[NCLS];
    if (rg == 0) {
        s = sp[0][k] + sp[1][k] + sp[2][k] + sp[3][k];
        g_s[k][d] = s;
        float c = (float)g_counts[k];
        sh1[k] = s * s; sh2[k] = s; sh3[k] = c * c;
        sh4[k] = g_Apart[k][d];          // thread k doubles as rc=k (RCH==NCLS==64)
        sh5[k] = g_Qpart[k][d];
    }
    __syncthreads();
    for (int off = 32; off > 0; off >>= 1) {
        if (t < off) {
            sh1[t] += sh1[t + off]; sh2[t] += sh2[t + off]; sh3[t] += sh3[t + off];
            sh4[t] += sh4[t + off]; sh5[t] += sh5[t + off];
        }
        __syncthreads();
    }

    if (t == 0) {
        float ssum2 = sh1[0], stot = sh2[0], sumc2 = sh3[0];
        float a = sh4[0], q = sh5[0];
        float cntpos = sumc2 - (float)NPTS;
        float cntneg = (float)NPTS * (float)NPTS - sumc2;
        float sum_pos = 2.f * a - 2.f * ssum2;
        float sum_neg = 2.f * (float)NPTS * q - 2.f * a - 2.f * stot * stot + 2.f * ssum2;
        g_w[d] = cntneg / (sum_neg + EPSV) - cntpos / (sum_pos + EPSV);
    }
}

__global__ void k_wss() {
    int k = blockIdx.x, t = threadIdx.x;
    float p = 0.f;
    for (int d = t; d < DIMS; d += 256) { float s = g_s[k][d]; p = fmaf(g_w[d] * s, s, p); }
    __shared__ float red[256];
    red[t] = p; __syncthreads();
    for (int off = 128; off > 0; off >>= 1) { if (t < off) red[t] += red[t + off]; __syncthreads(); }
    if (t == 0) g_wss[k] = red[0];
}

// Quantize rows: xq = s8(x/sA_i), xwq = s8(w*x/sB_i); sq_i exact fp32; P_k += sq_i.
__global__ void k_xwsq(const float* __restrict__ X, const int* __restrict__ tgt) {
    int i = blockIdx.x, t = threadIdx.x;   // 256 threads, 4 dims each
    const float4* xr = (const float4*)(X + (size_t)i * DIMS);
    const float4* wr = (const float4*)g_w;
    float4 x4 = xr[t], w4 = wr[t], o;
    o.x = x4.x * w4.x; o.y = x4.y * w4.y; o.z = x4.z * w4.z; o.w = x4.w * w4.w;
    float acc = x4.x * o.x + x4.y * o.y + x4.z * o.z + x4.w * o.w;
    float mx = fmaxf(fmaxf(fabsf(x4.x), fabsf(x4.y)), fmaxf(fabsf(x4.z), fabsf(x4.w)));
    float mo = fmaxf(fmaxf(fabsf(o.x),  fabsf(o.y)),  fmaxf(fabsf(o.z),  fabsf(o.w)));

    __shared__ float rs[256], rx[256], ro[256];
    __shared__ float s_isx, s_iso;
    rs[t] = acc; rx[t] = mx; ro[t] = mo;
    __syncthreads();
    for (int off = 128; off > 0; off >>= 1) {
        if (t < off) {
            rs[t] += rs[t + off];
            rx[t] = fmaxf(rx[t], rx[t + off]);
            ro[t] = fmaxf(ro[t], ro[t + off]);
        }
        __syncthreads();
    }
    if (t == 0) {
        float sx = fmaxf(rx[0], 1e-20f) / 127.f;
        float so = fmaxf(ro[0], 1e-20f) / 127.f;
        g_sA[i] = sx; g_sB[i] = so;
        s_isx = 1.f / sx; s_iso = 1.f / so;
        g_sq[i] = rs[0];
        atomicAdd(&g_P[tgt[i]], rs[0]);
    }
    __syncthreads();
    float isx = s_isx, iso = s_iso;
    char4 qx, qo;
    qx.x = (signed char)__float2int_rn(x4.x * isx);
    qx.y = (signed char)__float2int_rn(x4.y * isx);
    qx.z = (signed char)__float2int_rn(x4.z * isx);
    qx.w = (signed char)__float2int_rn(x4.w * isx);
    qo.x = (signed char)__float2int_rn(o.x * iso);
    qo.y = (signed char)__float2int_rn(o.y * iso);
    qo.z = (signed char)__float2int_rn(o.z * iso);
    qo.w = (signed char)__float2int_rn(o.w * iso);
    ((char4*)(g_xq  + (size_t)i * DIMS))[t] = qx;
    ((char4*)(g_xwq + (size_t)i * DIMS))[t] = qo;
}

// ------------------------------------------------------------------
// int8 mma.sync fused Gram + softplus. 256x128 tile, BK=128 int8, 3-stage
// cp.async, ldmatrix.x4 (b16 view of s8 tiles), 8 warps (4m x 2n) each 64x64.
__device__ __forceinline__ void load_stage(uint32_t sA, uint32_t sB,
                                           const signed char* Ag,
                                           const signed char* Bg,
                                           int kt, int t) {
    int seg = t & 7;               // 16B segment within 128B row
    int r0  = t >> 3;              // 32 rows per pass
    #pragma unroll
    for (int p = 0; p < 8; p++) {  // A: 256 rows
        int row = r0 + 32 * p;
        cp16(sA + row * (uint32_t)LSTRB + seg * 16u, Ag + (size_t)row * DIMS + kt + seg * 16);
    }
    #pragma unroll
    for (int p = 0; p < 4; p++) {  // B: 128 rows
        int row = r0 + 32 * p;
        cp16(sB + row * (uint32_t)LSTRB + seg * 16u, Bg + (size_t)row * DIMS + kt + seg * 16);
    }
    asm volatile("cp.async.commit_group;" ::: "memory");
}

__global__ void __launch_bounds__(256) k_main() {
    // map linear block id -> (bi, bj) on the triangle bj >= 2*bi
    int L = blockIdx.x, bi = 0, cnt = 32;
    while (L >= cnt) { L -= cnt; bi++; cnt -= 2; }
    int bj = 2 * bi + L;
    int iBase = bi * BM, jBase = bj * BN;

    extern __shared__ char dsmem[];
    __shared__ float red[256];
    __shared__ float sqi_sh[BM], sqj_sh[BN];
    __shared__ float sai_sh[BM], sbj_sh[BN];

    int t = threadIdx.x;
    int lane = t & 31, w = t >> 5;
    int warpRow = w & 3, warpCol = w >> 2;    // 4 x 2 warps
    uint32_t sbase = smem_u32(dsmem);

    const signed char* Ag = g_xq  + (size_t)iBase * DIMS;
    const signed char* Bg = g_xwq + (size_t)jBase * DIMS;

    // prefetch sq + scales for the epilogue
    sqi_sh[t] = g_sq[iBase + t];
    sai_sh[t] = g_sA[iBase + t];
    if (t < BN) { sqj_sh[t] = g_sq[jBase + t]; sbj_sh[t] = g_sB[jBase + t]; }

    int acc[4][8][4];
    #pragma unroll
    for (int mf = 0; mf < 4; mf++)
        #pragma unroll
        for (int nf = 0; nf < 8; nf++)
            #pragma unroll
            for (int q = 0; q < 4; q++) acc[mf][nf][q] = 0;

    // prologue: chunks 0 and 1 into stages 0 and 1
    load_stage(sbase,        sbase + A_BYTES,        Ag, Bg, 0,  t);
    load_stage(sbase + STGB, sbase + STGB + A_BYTES, Ag, Bg, BK, t);

    // fragment address components (b16 view: identical to bf16 addressing)
    uint32_t aRow = (uint32_t)(warpRow * 64 + (lane & 15));
    uint32_t aKof = (uint32_t)((lane >> 4) * 16);
    int grp = lane >> 3;
    uint32_t bRowB = (uint32_t)(warpCol * 64 + ((grp >> 1) << 3) + (lane & 7));
    uint32_t bKof = (uint32_t)((grp & 1) * 16);

    for (int c = 0; c < NCH; c++) {
        uint32_t sA = sbase + (uint32_t)(c % NSTG) * STGB;
        uint32_t sB = sA + A_BYTES;
        if (c + 2 < NCH) asm volatile("cp.async.wait_group 1;" ::: "memory");
        else             asm volatile("cp.async.wait_group 0;" ::: "memory");
        __syncthreads();

        if (c + 2 < NCH)
            load_stage(sbase + (uint32_t)((c + 2) % NSTG) * STGB,
                       sbase + (uint32_t)((c + 2) % NSTG) * STGB + A_BYTES,
                       Ag, Bg, (c + 2) * BK, t);

        #pragma unroll
        for (int ks = 0; ks < 4; ks++) {      // each ks = 32 int8 k-dims = 32 B
            uint32_t a[4][4], b[8][2];
            #pragma unroll
            for (int nfp = 0; nfp < 4; nfp++) {
                uint32_t addr = sB + (bRowB + nfp * 16) * (uint32_t)LSTRB + ks * 32u + bKof;
                ldm_x4(b[2 * nfp][0], b[2 * nfp][1], b[2 * nfp + 1][0], b[2 * nfp + 1][1], addr);
            }
            #pragma unroll
            for (int mf = 0; mf < 4; mf++) {
                uint32_t addr = sA + (aRow + mf * 16) * (uint32_t)LSTRB + ks * 32u + aKof;
                ldm_x4(a[mf][0], a[mf][1], a[mf][2], a[mf][3], addr);
            }
            #pragma unroll
            for (int mf = 0; mf < 4; mf++)
                #pragma unroll
                for (int nf = 0; nf < 8; nf++)
                    mma_s8(acc[mf][nf], a[mf][0], a[mf][1], a[mf][2], a[mf][3],
                           b[nf][0], b[nf][1]);
        }
        __syncthreads();
    }

    // epilogue: S = sq_i + sq_j - 2*sA_i*sB_j*G_int, softplus over strict triangle
    int g = lane >> 2, tg = lane & 3;
    float sqj[8][2], sbj[8][2];
    int jc[8];
    #pragma unroll
    for (int nf = 0; nf < 8; nf++) {
        int jl = warpCol * 64 + nf * 8 + 2 * tg;
        jc[nf] = jBase + jl;
        sqj[nf][0] = sqj_sh[jl];     sqj[nf][1] = sqj_sh[jl + 1];
        sbj[nf][0] = sbj_sh[jl];     sbj[nf][1] = sbj_sh[jl + 1];
    }

    float lsum = 0.f;
    #pragma unroll
    for (int mf = 0; mf < 4; mf++) {
        int il = warpRow * 64 + mf * 16 + g;
        int i0 = iBase + il;
        float sqi0 = sqi_sh[il], sqi1 = sqi_sh[il + 8];
        float sa0 = -2.f * sai_sh[il], sa1 = -2.f * sai_sh[il + 8];
        #pragma unroll
        for (int nf = 0; nf < 8; nf++) {
            int j0 = jc[nf];
            float S;
            if (i0 < j0) {
                S = sqi0 + sqj[nf][0] + sa0 * sbj[nf][0] * (float)acc[mf][nf][0];
                lsum += fmaxf(S, 0.f) + __logf(1.f + __expf(-fabsf(S)));
            }
            if (i0 < j0 + 1) {
                S = sqi0 + sqj[nf][1] + sa0 * sbj[nf][1] * (float)acc[mf][nf][1];
                lsum += fmaxf(S, 0.f) + __logf(1.f + __expf(-fabsf(S)));
            }
            if (i0 + 8 < j0) {
                S = sqi1 + sqj[nf][0] + sa1 * sbj[nf][0] * (float)acc[mf][nf][2];
                lsum += fmaxf(S, 0.f) + __logf(1.f + __expf(-fabsf(S)));
            }
            if (i0 + 8 < j0 + 1) {
                S = sqi1 + sqj[nf][1] + sa1 * sbj[nf][1] * (float)acc[mf][nf][3];
                lsum += fmaxf(S, 0.f) + __logf(1.f + __expf(-fabsf(S)));
            }
        }
    }

    red[t] = lsum; __syncthreads();
    for (int off = 128; off > 0; off >>= 1) { if (t < off) red[t] += red[t + off]; __syncthreads(); }
    if (t == 0) atomicAdd(&g_pairsum, (double)red[0]);
}

// loss = (2*pairsum - sum_k (2 c_k P_k - 2 wss_k)) / (N(N-1))
__global__ void k_final(float* __restrict__ out) {
    __shared__ float red[NCLS];
    int t = threadIdx.x;
    float c = (float)g_counts[t];
    red[t] = 2.f * c * g_P[t] - 2.f * g_wss[t];
    __syncthreads();
    if (t == 0) {
        double ts = 0.0;
        for (int k = 0; k < NCLS; k++) ts += (double)red[k];
        double denom = (double)NPTS * (double)(NPTS - 1);
        out[0] = (float)((2.0 * g_pairsum - ts) / denom);
    }
}

// ------------------------------------------------------------------
extern "C" void kernel_launch(void* const* d_in, const int* in_sizes, int n_in,
                              void* d_out, int out_size) {
    const float* X   = (const float*)d_in[0];
    const int*   tgt = (const int*)d_in[1];
    float*       out = (float*)d_out;
    (void)in_sizes; (void)n_in; (void)out_size;

    cudaFuncSetAttribute(k_main, cudaFuncAttributeMaxDynamicSharedMemorySize, DSMEM_BYTES);

    k_zero<<<1, 128>>>();
    k_count<<<NPTS / 256, 256>>>(tgt);
    k_phase1<<<dim3(NDCH, RCH), 64>>>(X, tgt);
    k_reduce_w<<<DIMS, 256>>>();
    k_wss<<<NCLS, 256>>>();
    k_xwsq<<<NPTS, 256>>>(X, tgt);
    k_main<<<NTILES, 256, DSMEM_BYTES>>>();
    k_final<<<1, NCLS>>>(out);
}

// round 13
// speedup vs baseline: 1.7721x; 1.7721x over previous
#include <cuda_runtime.h>
#include <cuda_bf16.h>
#include <cstdint>

#define NPTS 4096
#define DIMS 1024
#define NCLS 64
#define EPSV 0.1f

#define RCH  64                 // row chunks for phase-1 partials
#define RPC  (NPTS / RCH)       // 64 rows per chunk
#define DCH  64                 // dims per phase-1 block
#define NDCH (DIMS / DCH)       // 16

// k_main tiling (bf16 mma.sync m16n8k16)
#define BM   256
#define BN   128
#define BK   64                 // bf16 elems per chunk = 128 B per row
#define NCH  (DIMS / BK)        // 16 chunks
#define NTILES 272              // triangle tiles: sum_{bi<16} (32 - 2*bi)
#define LSTRH 72                // smem row stride in halfs (144 B)
#define A_BYTES (BM * LSTRH * 2)   // 36864
#define B_BYTES (BN * LSTRH * 2)   // 18432
#define STGB  (A_BYTES + B_BYTES)  // 55296 B per stage
#define NSTG  4
#define DSMEM_BYTES (NSTG * STGB)  // 221184 B

// ---- static device scratch (no allocations allowed) ----
__device__ int      g_counts[NCLS];
__device__ float    g_spart[DIMS][RCH][NCLS];   // 16 MB partials, contiguous per dim
__device__ float    g_Apart[RCH][DIMS];
__device__ float    g_Qpart[RCH][DIMS];
__device__ float    g_s[NCLS][DIMS];
__device__ float    g_w[DIMS];
__device__ unsigned short g_xh[(size_t)NPTS * DIMS];   // bf16(x)
__device__ unsigned short g_xwh[(size_t)NPTS * DIMS];  // bf16(w*x)
__device__ float    g_sq[NPTS];                 // sq_i = sum_d w_d x_id^2 (fp32 exact)
__device__ float    g_P[NCLS];
__device__ float    g_wss[NCLS];
__device__ double   g_pairsum;

// ---------------- helpers ----------------
__device__ __forceinline__ uint32_t smem_u32(const void* p) {
    uint32_t a;
    asm("{ .reg .u64 t; cvta.to.shared.u64 t, %1; cvt.u32.u64 %0, t; }" : "=r"(a) : "l"(p));
    return a;
}
__device__ __forceinline__ void cp16(uint32_t dst, const void* src) {
    asm volatile("cp.async.cg.shared.global [%0], [%1], 16;" :: "r"(dst), "l"(src) : "memory");
}
__device__ __forceinline__ void ldm_x4(uint32_t& r0, uint32_t& r1, uint32_t& r2, uint32_t& r3,
                                       uint32_t addr) {
    asm volatile("ldmatrix.sync.aligned.m8n8.x4.shared.b16 {%0,%1,%2,%3}, [%4];"
                 : "=r"(r0), "=r"(r1), "=r"(r2), "=r"(r3) : "r"(addr));
}
__device__ __forceinline__ void mma_bf16(float* c, uint32_t a0, uint32_t a1, uint32_t a2,
                                         uint32_t a3, uint32_t b0, uint32_t b1) {
    asm volatile("mma.sync.aligned.m16n8k16.row.col.f32.bf16.bf16.f32 "
                 "{%0,%1,%2,%3}, {%4,%5,%6,%7}, {%8,%9}, {%0,%1,%2,%3};"
                 : "+f"(c[0]), "+f"(c[1]), "+f"(c[2]), "+f"(c[3])
                 : "r"(a0), "r"(a1), "r"(a2), "r"(a3), "r"(b0), "r"(b1));
}

// ------------------------------------------------------------------
__global__ void k_zero() {
    int t = threadIdx.x;
    if (t < NCLS) { g_counts[t] = 0; g_P[t] = 0.f; g_wss[t] = 0.f; }
    if (t == NCLS) g_pairsum = 0.0;
}

__global__ void k_count(const int* __restrict__ tgt) {
    int i = blockIdx.x * blockDim.x + threadIdx.x;
    if (i < NPTS) atomicAdd(&g_counts[tgt[i]], 1);
}

__global__ void k_phase1(const float* __restrict__ X, const int* __restrict__ tgt) {
    __shared__ float s_sh[NCLS * DCH];
    __shared__ float cnt_sh[NCLS];
    __shared__ int   tg_sh[RPC];
    int t  = threadIdx.x;                // 0..63
    int dc = blockIdx.x, rc = blockIdx.y;

    for (int i = t; i < NCLS * DCH; i += 64) s_sh[i] = 0.f;
    cnt_sh[t] = (float)g_counts[t];
    if (t < RPC) tg_sh[t] = tgt[rc * RPC + t];
    __syncthreads();

    const float* xp = X + (size_t)(rc * RPC) * DIMS + dc * DCH + t;
    float aacc = 0.f, qacc = 0.f;
    #pragma unroll 8
    for (int r = 0; r < RPC; r++) {
        float v = xp[(size_t)r * DIMS];
        int   k = tg_sh[r];
        s_sh[k * DCH + t] += v;
        float v2 = v * v;
        qacc += v2;
        aacc = fmaf(cnt_sh[k], v2, aacc);
    }
    __syncthreads();

    int d = dc * DCH + t;
    #pragma unroll
    for (int k4 = 0; k4 < NCLS; k4 += 4) {
        float4 v = make_float4(s_sh[(k4 + 0) * DCH + t], s_sh[(k4 + 1) * DCH + t],
                               s_sh[(k4 + 2) * DCH + t], s_sh[(k4 + 3) * DCH + t]);
        *(float4*)&g_spart[d][rc][k4] = v;
    }
    g_Apart[rc][d] = aacc;
    g_Qpart[rc][d] = qacc;
}

// 256 threads: block d streams its contiguous 16KB partial slab, computes w_d,
// and folds the wss contribution (atomicAdd per class).
__global__ void k_reduce_w() {
    int d = blockIdx.x, t = threadIdx.x;
    int k = t & 63, rg = t >> 6;         // class, rc-group

    float s = 0.f;
    #pragma unroll
    for (int rc = rg * 16; rc < rg * 16 + 16; rc++) s += g_spart[d][rc][k];
    __shared__ float sp[4][NCLS];
    sp[rg][k] = s;
    __syncthreads();

    __shared__ float sh1[NCLS], sh2[NCLS], sh3[NCLS], sh4[NCLS], sh5[NCLS];
    __shared__ float s_k[NCLS];
    __shared__ float s_wd;
    if (rg == 0) {
        s = sp[0][k] + sp[1][k] + sp[2][k] + sp[3][k];
        g_s[k][d] = s;
        s_k[k] = s;
        float c = (float)g_counts[k];
        sh1[k] = s * s; sh2[k] = s; sh3[k] = c * c;
        sh4[k] = g_Apart[k][d];          // thread k doubles as rc=k (RCH==NCLS==64)
        sh5[k] = g_Qpart[k][d];
    }
    __syncthreads();
    for (int off = 32; off > 0; off >>= 1) {
        if (t < off) {
            sh1[t] += sh1[t + off]; sh2[t] += sh2[t + off]; sh3[t] += sh3[t + off];
            sh4[t] += sh4[t + off]; sh5[t] += sh5[t + off];
        }
        __syncthreads();
    }

    if (t == 0) {
        float ssum2 = sh1[0], stot = sh2[0], sumc2 = sh3[0];
        float a = sh4[0], q = sh5[0];
        float cntpos = sumc2 - (float)NPTS;
        float cntneg = (float)NPTS * (float)NPTS - sumc2;
        float sum_pos = 2.f * a - 2.f * ssum2;
        float sum_neg = 2.f * (float)NPTS * q - 2.f * a - 2.f * stot * stot + 2.f * ssum2;
        s_wd = cntneg / (sum_neg + EPSV) - cntpos / (sum_pos + EPSV);
        g_w[d] = s_wd;
    }
    __syncthreads();
    if (t < NCLS) {                      // fused wss: wss_k += w_d * s_kd^2
        float s0 = s_k[t];
        atomicAdd(&g_wss[t], s_wd * s0 * s0);
    }
}

// xh = bf16(x), xwh = bf16(w*x), sq_i = sum w x^2 (fp32), P_k += sq_i
__global__ void k_xwsq(const float* __restrict__ X, const int* __restrict__ tgt) {
    int i = blockIdx.x, t = threadIdx.x;   // 256 threads, 4 dims each
    const float4* xr = (const float4*)(X + (size_t)i * DIMS);
    const float4* wr = (const float4*)g_w;
    float4 x4 = xr[t], w4 = wr[t], o;
    o.x = x4.x * w4.x; o.y = x4.y * w4.y; o.z = x4.z * w4.z; o.w = x4.w * w4.w;
    float acc = x4.x * o.x + x4.y * o.y + x4.z * o.z + x4.w * o.w;

    __nv_bfloat162 hx0 = __floats2bfloat162_rn(x4.x, x4.y);
    __nv_bfloat162 hx1 = __floats2bfloat162_rn(x4.z, x4.w);
    __nv_bfloat162 ho0 = __floats2bfloat162_rn(o.x, o.y);
    __nv_bfloat162 ho1 = __floats2bfloat162_rn(o.z, o.w);
    uint2* dxh  = (uint2*)(g_xh  + (size_t)i * DIMS);
    uint2* dxwh = (uint2*)(g_xwh + (size_t)i * DIMS);
    uint2 px, po;
    px.x = *(uint32_t*)&hx0; px.y = *(uint32_t*)&hx1;
    po.x = *(uint32_t*)&ho0; po.y = *(uint32_t*)&ho1;
    dxh[t] = px; dxwh[t] = po;

    __shared__ float red[256];
    red[t] = acc; __syncthreads();
    for (int off = 128; off > 0; off >>= 1) { if (t < off) red[t] += red[t + off]; __syncthreads(); }
    if (t == 0) { g_sq[i] = red[0]; atomicAdd(&g_P[tgt[i]], red[0]); }
}

// ------------------------------------------------------------------
// bf16 mma.sync fused Gram + softplus. 256x128 tile, BK=64, 4-stage cp.async
// (one __syncthreads per chunk), ldmatrix.x4 fragments, 8 warps (4m x 2n).
__device__ __forceinline__ void load_stage(uint32_t sA, uint32_t sB,
                                           const unsigned short* Ag,
                                           const unsigned short* Bg,
                                           int kt, int t) {
    int seg = t & 7;               // 16B segment within 128B row
    int r0  = t >> 3;              // 32 rows per pass
    #pragma unroll
    for (int p = 0; p < 8; p++) {  // A: 256 rows
        int row = r0 + 32 * p;
        cp16(sA + row * 144u + seg * 16u, Ag + (size_t)row * DIMS + kt + seg * 8);
    }
    #pragma unroll
    for (int p = 0; p < 4; p++) {  // B: 128 rows
        int row = r0 + 32 * p;
        cp16(sB + row * 144u + seg * 16u, Bg + (size_t)row * DIMS + kt + seg * 8);
    }
    asm volatile("cp.async.commit_group;" ::: "memory");
}

__global__ void __launch_bounds__(256) k_main() {
    // map linear block id -> (bi, bj) on the triangle bj >= 2*bi
    int L = blockIdx.x, bi = 0, cnt = 32;
    while (L >= cnt) { L -= cnt; bi++; cnt -= 2; }
    int bj = 2 * bi + L;
    int iBase = bi * BM, jBase = bj * BN;

    extern __shared__ char dsmem[];
    __shared__ float red[256];
    __shared__ float sqi_sh[BM];
    __shared__ float sqj_sh[BN];

    int t = threadIdx.x;
    int lane = t & 31, w = t >> 5;
    int warpRow = w & 3, warpCol = w >> 2;    // 4 x 2 warps
    uint32_t sbase = smem_u32(dsmem);

    const unsigned short* Ag = g_xh  + (size_t)iBase * DIMS;
    const unsigned short* Bg = g_xwh + (size_t)jBase * DIMS;

    // prefetch sq rows/cols for the epilogue
    sqi_sh[t] = g_sq[iBase + t];
    if (t < BN) sqj_sh[t] = g_sq[jBase + t];

    float acc[4][8][4];
    #pragma unroll
    for (int mf = 0; mf < 4; mf++)
        #pragma unroll
        for (int nf = 0; nf < 8; nf++)
            #pragma unroll
            for (int q = 0; q < 4; q++) acc[mf][nf][q] = 0.f;

    // prologue: chunks 0..2 into stages 0..2
    load_stage(sbase,            sbase + A_BYTES,            Ag, Bg, 0,      t);
    load_stage(sbase + STGB,     sbase + STGB + A_BYTES,     Ag, Bg, BK,     t);
    load_stage(sbase + 2 * STGB, sbase + 2 * STGB + A_BYTES, Ag, Bg, 2 * BK, t);

    // precomputed fragment address components
    uint32_t aRow = (uint32_t)(warpRow * 64 + (lane & 15));
    uint32_t aKof = (uint32_t)((lane >> 4) * 16);
    int grp = lane >> 3;
    uint32_t bRowB = (uint32_t)(warpCol * 64 + ((grp >> 1) << 3) + (lane & 7));
    uint32_t bKof = (uint32_t)((grp & 1) * 16);

    for (int c = 0; c < NCH; c++) {
        uint32_t sA = sbase + (uint32_t)(c % NSTG) * STGB;
        uint32_t sB = sA + A_BYTES;
        if (c + 3 < NCH) asm volatile("cp.async.wait_group 2;" ::: "memory");
        else             asm volatile("cp.async.wait_group 0;" ::: "memory");
        __syncthreads();          // single barrier per chunk (4-stage ring)

        if (c + 3 < NCH)
            load_stage(sbase + (uint32_t)((c + 3) % NSTG) * STGB,
                       sbase + (uint32_t)((c + 3) % NSTG) * STGB + A_BYTES,
                       Ag, Bg, (c + 3) * BK, t);

        #pragma unroll
        for (int ks = 0; ks < 4; ks++) {
            uint32_t a[4][4], b[8][2];
            #pragma unroll
            for (int nfp = 0; nfp < 4; nfp++) {
                uint32_t addr = sB + (bRowB + nfp * 16) * 144u + ks * 32u + bKof;
                ldm_x4(b[2 * nfp][0], b[2 * nfp][1], b[2 * nfp + 1][0], b[2 * nfp + 1][1], addr);
            }
            #pragma unroll
            for (int mf = 0; mf < 4; mf++) {
                uint32_t addr = sA + (aRow + mf * 16) * 144u + ks * 32u + aKof;
                ldm_x4(a[mf][0], a[mf][1], a[mf][2], a[mf][3], addr);
            }
            #pragma unroll
            for (int mf = 0; mf < 4; mf++)
                #pragma unroll
                for (int nf = 0; nf < 8; nf++)
                    mma_bf16(acc[mf][nf], a[mf][0], a[mf][1], a[mf][2], a[mf][3],
                             b[nf][0], b[nf][1]);
        }
    }

    // epilogue: S = sq_i + sq_j - 2G, softplus over strict upper triangle
    int g = lane >> 2, tg = lane & 3;
    float sqj[8][2];
    int jc[8];
    #pragma unroll
    for (int nf = 0; nf < 8; nf++) {
        int jl = warpCol * 64 + nf * 8 + 2 * tg;
        jc[nf] = jBase + jl;
        sqj[nf][0] = sqj_sh[jl];
        sqj[nf][1] = sqj_sh[jl + 1];
    }

    float lsum = 0.f;
    #pragma unroll
    for (int mf = 0; mf < 4; mf++) {
        int il = warpRow * 64 + mf * 16 + g;
        int i0 = iBase + il;
        float sqi0 = sqi_sh[il], sqi1 = sqi_sh[il + 8];
        #pragma unroll
        for (int nf = 0; nf < 8; nf++) {
            int j0 = jc[nf];
            float S;
            if (i0 < j0) {
                S = sqi0 + sqj[nf][0] - 2.f * acc[mf][nf][0];
                lsum += fmaxf(S, 0.f) + __logf(1.f + __expf(-fabsf(S)));
            }
            if (i0 < j0 + 1) {
                S = sqi0 + sqj[nf][1] - 2.f * acc[mf][nf][1];
                lsum += fmaxf(S, 0.f) + __logf(1.f + __expf(-fabsf(S)));
            }
            if (i0 + 8 < j0) {
                S = sqi1 + sqj[nf][0] - 2.f * acc[mf][nf][2];
                lsum += fmaxf(S, 0.f) + __logf(1.f + __expf(-fabsf(S)));
            }
            if (i0 + 8 < j0 + 1) {
                S = sqi1 + sqj[nf][1] - 2.f * acc[mf][nf][3];
                lsum += fmaxf(S, 0.f) + __logf(1.f + __expf(-fabsf(S)));
            }
        }
    }

    red[t] = lsum; __syncthreads();
    for (int off = 128; off > 0; off >>= 1) { if (t < off) red[t] += red[t + off]; __syncthreads(); }
    if (t == 0) atomicAdd(&g_pairsum, (double)red[0]);
}

// loss = (2*pairsum - sum_k (2 c_k P_k - 2 wss_k)) / (N(N-1))
__global__ void k_final(float* __restrict__ out) {
    __shared__ float red[NCLS];
    int t = threadIdx.x;
    float c = (float)g_counts[t];
    red[t] = 2.f * c * g_P[t] - 2.f * g_wss[t];
    __syncthreads();
    if (t == 0) {
        double ts = 0.0;
        for (int k = 0; k < NCLS; k++) ts += (double)red[k];
        double denom = (double)NPTS * (double)(NPTS - 1);
        out[0] = (float)((2.0 * g_pairsum - ts) / denom);
    }
}

// ------------------------------------------------------------------
extern "C" void kernel_launch(void* const* d_in, const int* in_sizes, int n_in,
                              void* d_out, int out_size) {
    const float* X   = (const float*)d_in[0];
    const int*   tgt = (const int*)d_in[1];
    float*       out = (float*)d_out;
    (void)in_sizes; (void)n_in; (void)out_size;

    cudaFuncSetAttribute(k_main, cudaFuncAttributeMaxDynamicSharedMemorySize, DSMEM_BYTES);

    k_zero<<<1, 128>>>();
    k_count<<<NPTS / 256, 256>>>(tgt);
    k_phase1<<<dim3(NDCH, RCH), 64>>>(X, tgt);
    k_reduce_w<<<DIMS, 256>>>();
    k_xwsq<<<NPTS, 256>>>(X, tgt);
    k_main<<<NTILES, 256, DSMEM_BYTES>>>();
    k_final<<<1, NCLS>>>(out);
}